// round 10
// baseline (speedup 1.0000x reference)
#include <cuda_runtime.h>

// TSM for fixed shape x=[8,16,96,112,112] fp32, k=4, elements=3.
//   c%3==0: out[t] = (t < 12) ? 0 : x[t]
//   c%3==1: out[t] = (t <  4) ? 0 : x[t-4]
//   c%3==2: out[t] = x[t]
//
// FINAL config — empirical best across 9 measured variants (145.9us kernel,
// 84.1% DRAM, 6.67 TB/s, rel_err 0.0):
//   - Plane (b,t,c) = 12544 floats = 3136 float4; work unit = HALF plane.
//   - 224 threads x 7 float4, single front-batched load group (MLP=7).
//   - Natural register allocation (32 regs, ~7-9 CTAs/SM).
//   - Plain non-persistent launch: hardware dispatches blocks in address
//     order, keeping concurrent DRAM traffic spatially dense (persistent
//     grid-stride blocks measured 72% DRAM vs 84%).
//   - No .cs hints / no v8 accesses: both measured neutral.
// Workload is pinned at the HBM mixed read/write ceiling (~84% of spec):
// occ 33-78%, MLP 4-7, 16B/32B widths all produce identical bandwidth.

static constexpr int B = 8;
static constexpr int T = 16;
static constexpr int C = 96;
static constexpr int HW = 112 * 112;          // 12544
static constexpr int VEC_PER_PLANE = HW / 4;  // 3136
static constexpr int K_SHIFT = 4;
static constexpr int PLANES = B * T * C;      // 12288
static constexpr int THREADS = 224;
static constexpr int VPT = 7;                 // 224*7 = 1568 = plane/2
static constexpr int HALF_VEC = THREADS * VPT;

__global__ __launch_bounds__(THREADS)
void tsm_kernel(const float4* __restrict__ x, float4* __restrict__ out) {
    const int blk   = blockIdx.x;
    const int plane = blk >> 1;
    const int half  = blk & 1;

    const int c = plane % C;
    const int t = (plane / C) % T;
    const int m = c % 3;

    const long long base = (long long)plane * VEC_PER_PLANE
                         + half * HALF_VEC + threadIdx.x;
    float4* __restrict__ o = out + base;

    const bool zero = (m == 0 && t < T - K_SHIFT) || (m == 1 && t < K_SHIFT);

    if (zero) {
        const float4 z = make_float4(0.f, 0.f, 0.f, 0.f);
        #pragma unroll
        for (int i = 0; i < VPT; i++)
            o[i * THREADS] = z;
    } else {
        const float4* __restrict__ src = x + base
            - (m == 1 ? (long long)K_SHIFT * C * VEC_PER_PLANE : 0LL);
        float4 v[VPT];
        #pragma unroll
        for (int i = 0; i < VPT; i++)
            v[i] = src[i * THREADS];
        #pragma unroll
        for (int i = 0; i < VPT; i++)
            o[i * THREADS] = v[i];
    }
}

extern "C" void kernel_launch(void* const* d_in, const int* in_sizes, int n_in,
                              void* d_out, int out_size) {
    const float4* x = (const float4*)d_in[0];
    float4* out = (float4*)d_out;
    tsm_kernel<<<PLANES * 2, THREADS>>>(x, out);
}

// round 11
// speedup vs baseline: 1.0015x; 1.0015x over previous
#include <cuda_runtime.h>

// TSM for fixed shape x=[8,16,96,112,112] fp32, k=4, elements=3.
//   c%3==0: out[t] = (t < 12) ? 0 : x[t]
//   c%3==1: out[t] = (t <  4) ? 0 : x[t-4]
//   c%3==2: out[t] = x[t]
//
// FINAL: exact source of the best measured bench (152.1us end-to-end,
// 146.0us kernel, 84.0% DRAM, 6.66 TB/s, rel_err 0.0).
//   - Plane (b,t,c) = 12544 floats = 3136 float4; work unit = HALF plane.
//   - 224 threads x 7 float4, single front-batched load group (MLP=7).
//   - __ldcs/__stcs streaming hints (zero reuse -> evict-first).
//   - Natural register allocation (38 regs -> 7 CTAs/SM): capping to 32 for
//     9 CTAs/SM measured equal-or-worse (cross-CTA L1tex contention).
//   - Plain non-persistent launch: hardware dispatches blocks in address
//     order, keeping concurrent DRAM traffic spatially dense (persistent
//     grid-stride blocks measured 72% DRAM vs 84%).
// Ten measured variants (occ 33-78%, MLP 4-7, 16/32B widths) all land at
// 146-148us kernel: the HBM mixed read/write ceiling for this pattern.

static constexpr int B = 8;
static constexpr int T = 16;
static constexpr int C = 96;
static constexpr int HW = 112 * 112;          // 12544
static constexpr int VEC_PER_PLANE = HW / 4;  // 3136
static constexpr int K_SHIFT = 4;
static constexpr int PLANES = B * T * C;      // 12288
static constexpr int THREADS = 224;
static constexpr int VPT = 7;                 // 224*7 = 1568 = plane/2
static constexpr int HALF_VEC = THREADS * VPT;

__global__ __launch_bounds__(THREADS)
void tsm_kernel(const float4* __restrict__ x, float4* __restrict__ out) {
    const int blk   = blockIdx.x;
    const int plane = blk >> 1;
    const int half  = blk & 1;

    const int c = plane % C;
    const int t = (plane / C) % T;
    const int m = c % 3;

    const long long base = (long long)plane * VEC_PER_PLANE
                         + half * HALF_VEC + threadIdx.x;
    float4* __restrict__ o = out + base;

    const bool zero = (m == 0 && t < T - K_SHIFT) || (m == 1 && t < K_SHIFT);

    if (zero) {
        const float4 z = make_float4(0.f, 0.f, 0.f, 0.f);
        #pragma unroll
        for (int i = 0; i < VPT; i++)
            __stcs(&o[i * THREADS], z);
    } else {
        const float4* __restrict__ src = x + base
            - (m == 1 ? (long long)K_SHIFT * C * VEC_PER_PLANE : 0LL);
        float4 v[VPT];
        #pragma unroll
        for (int i = 0; i < VPT; i++)
            v[i] = __ldcs(&src[i * THREADS]);
        #pragma unroll
        for (int i = 0; i < VPT; i++)
            __stcs(&o[i * THREADS], v[i]);
    }
}

extern "C" void kernel_launch(void* const* d_in, const int* in_sizes, int n_in,
                              void* d_out, int out_size) {
    const float4* x = (const float4*)d_in[0];
    float4* out = (float4*)d_out;
    tsm_kernel<<<PLANES * 2, THREADS>>>(x, out);
}

// round 12
// speedup vs baseline: 1.0042x; 1.0027x over previous
#include <cuda_runtime.h>

// TSM for fixed shape x=[8,16,96,112,112] fp32, k=4, elements=3.
//   c%3==0: out[t] = (t < 12) ? 0 : x[t]
//   c%3==1: out[t] = (t <  4) ? 0 : x[t-4]
//   c%3==2: out[t] = x[t]
//
// FINAL. Best measured config (kernel 146.0-146.3us, 84% DRAM, 6.65 TB/s,
// rel_err 0.0; bench 152.1-153.5us across identical-source reruns = noise).
//   - Plane (b,t,c) = 12544 floats = 3136 float4; work unit = HALF plane.
//   - 224 threads x 7 float4, single front-batched load group (MLP=7).
//   - __ldcs/__stcs streaming hints (zero reuse -> evict-first).
//   - Natural register allocation; plain non-persistent launch keeps block
//     dispatch in address order (spatially dense DRAM traffic).
// 11 rounds establish the plateau: occ 33-78%, MLP 4-7, 16/32B widths,
// hints on/off, 224/448 threads, persistent vs dispatched — all land at
// 146-148us kernel. This is the HBM mixed read/write roofline; read and
// write traffic are both provably minimal for the operator.

static constexpr int B = 8;
static constexpr int T = 16;
static constexpr int C = 96;
static constexpr int HW = 112 * 112;          // 12544
static constexpr int VEC_PER_PLANE = HW / 4;  // 3136
static constexpr int K_SHIFT = 4;
static constexpr int PLANES = B * T * C;      // 12288
static constexpr int THREADS = 224;
static constexpr int VPT = 7;                 // 224*7 = 1568 = plane/2
static constexpr int HALF_VEC = THREADS * VPT;

__global__ __launch_bounds__(THREADS)
void tsm_kernel(const float4* __restrict__ x, float4* __restrict__ out) {
    const int blk   = blockIdx.x;
    const int plane = blk >> 1;
    const int half  = blk & 1;

    const int c = plane % C;
    const int t = (plane / C) % T;
    const int m = c % 3;

    const long long base = (long long)plane * VEC_PER_PLANE
                         + half * HALF_VEC + threadIdx.x;
    float4* __restrict__ o = out + base;

    const bool zero = (m == 0 && t < T - K_SHIFT) || (m == 1 && t < K_SHIFT);

    if (zero) {
        const float4 z = make_float4(0.f, 0.f, 0.f, 0.f);
        #pragma unroll
        for (int i = 0; i < VPT; i++)
            __stcs(&o[i * THREADS], z);
    } else {
        const float4* __restrict__ src = x + base
            - (m == 1 ? (long long)K_SHIFT * C * VEC_PER_PLANE : 0LL);
        float4 v[VPT];
        #pragma unroll
        for (int i = 0; i < VPT; i++)
            v[i] = __ldcs(&src[i * THREADS]);
        #pragma unroll
        for (int i = 0; i < VPT; i++)
            __stcs(&o[i * THREADS], v[i]);
    }
}

extern "C" void kernel_launch(void* const* d_in, const int* in_sizes, int n_in,
                              void* d_out, int out_size) {
    const float4* x = (const float4*)d_in[0];
    float4* out = (float4*)d_out;
    tsm_kernel<<<PLANES * 2, THREADS>>>(x, out);
}